// round 9
// baseline (speedup 1.0000x reference)
#include <cuda_runtime.h>

#define CIN  16
#define COUT 32
#define BSZ  8
#define S    24
#define SS   576
#define EPS  1e-5f

__device__ float g_mid[BSZ * SS * COUT * SS];
__device__ float g_stats[BSZ * 4 * 2];
__device__ float g_scale[BSZ * COUT];
__device__ float g_shift[BSZ * COUT];

__global__ void zero_stats_kernel() {
    if (threadIdx.x < BSZ * 8) g_stats[threadIdx.x] = 0.f;
}

// ---------------------------------------------------------------------------
// conv2: identical to the passing R6 version.
// ---------------------------------------------------------------------------
__global__ __launch_bounds__(512, 1)
void conv2_kernel(const float* __restrict__ x, const float* __restrict__ w2,
                  const float* __restrict__ b2) {
    extern __shared__ float sm[];
    float* s_img = sm;                  // [16][26][26] = 10816
    float* s_w   = sm + 10816;          // [ci][tap][co] = 4608
    float* s_red = sm + 10816 + 4608;   // 8

    const int bid  = blockIdx.x;
    const int b    = bid / SS;
    const int hawa = bid % SS;
    const int tid  = threadIdx.x;

    if (tid < 8) s_red[tid] = 0.f;
    for (int i = tid; i < CIN * 26 * 26; i += 512) s_img[i] = 0.f;
    for (int i = tid; i < CIN * 9 * COUT; i += 512) {
        int ci = i / 288; int tap = (i >> 5) % 9; int co = i & 31;
        s_w[i] = w2[(co * CIN + ci) * 9 + tap];
    }
    __syncthreads();
    for (int i = tid; i < CIN * SS; i += 512) {
        int ci = i / SS; int p = i - ci * SS;
        int hb = p / S, wb = p - hb * S;
        s_img[ci * 676 + (hb + 1) * 26 + (wb + 1)] =
            x[(((long)b * CIN + ci) * SS + hawa) * SS + p];
    }
    __syncthreads();

    const int cg = tid >> 6;
    const int pt = tid & 63;
    const int py = (pt >> 3) * 3;
    const int px = (pt & 7) * 3;

    float acc[9][4];
    #pragma unroll
    for (int j = 0; j < 4; j++) {
        float bb = __ldg(&b2[cg * 4 + j]);
        #pragma unroll
        for (int p = 0; p < 9; p++) acc[p][j] = bb;
    }

    for (int ci = 0; ci < CIN; ci++) {
        float wr[4][9];
        #pragma unroll
        for (int t = 0; t < 9; t++) {
            float4 wv = *(const float4*)&s_w[(ci * 9 + t) * 32 + cg * 4];
            wr[0][t] = wv.x; wr[1][t] = wv.y; wr[2][t] = wv.z; wr[3][t] = wv.w;
        }
        float in[5][5];
        #pragma unroll
        for (int dy = 0; dy < 5; dy++)
            #pragma unroll
            for (int dx = 0; dx < 5; dx++)
                in[dy][dx] = s_img[ci * 676 + (py + dy) * 26 + (px + dx)];
        #pragma unroll
        for (int oy = 0; oy < 3; oy++)
          #pragma unroll
          for (int ox = 0; ox < 3; ox++)
            #pragma unroll
            for (int ky = 0; ky < 3; ky++)
              #pragma unroll
              for (int kx = 0; kx < 3; kx++) {
                float v = in[oy + ky][ox + kx];
                int t = ky * 3 + kx;
                #pragma unroll
                for (int j = 0; j < 4; j++)
                    acc[oy * 3 + ox][j] += v * wr[j][t];
              }
    }

    float s = 0.f, sq = 0.f;
    float* midb = g_mid + (long)(b * SS + hawa) * COUT * SS;
    #pragma unroll
    for (int oy = 0; oy < 3; oy++)
      #pragma unroll
      for (int ox = 0; ox < 3; ox++) {
        int hbwb = (py + oy) * S + (px + ox);
        #pragma unroll
        for (int j = 0; j < 4; j++) {
            float v = acc[oy * 3 + ox][j];
            s += v; sq += v * v;
            midb[(cg * 4 + j) * SS + hbwb] = v;
        }
      }
    atomicAdd(&s_red[(cg >> 1) * 2],     s);
    atomicAdd(&s_red[(cg >> 1) * 2 + 1], sq);
    __syncthreads();
    if (tid < 8) atomicAdd(&g_stats[b * 8 + tid], s_red[tid]);
}

// ---------------------------------------------------------------------------
__global__ void finalize_kernel(const float* __restrict__ gamma,
                                const float* __restrict__ beta) {
    int tid = threadIdx.x;
    if (tid >= BSZ * COUT) return;
    int b = tid >> 5, c = tid & 31, g = c >> 3;
    const float n = (float)(8 * SS * SS);
    float s  = g_stats[b * 8 + g * 2];
    float ss = g_stats[b * 8 + g * 2 + 1];
    float mean = s / n;
    float var  = ss / n - mean * mean;
    float sc = gamma[c] * rsqrtf(var + EPS);
    g_scale[tid] = sc;
    g_shift[tid] = beta[c] - mean * sc;
}

// ---------------------------------------------------------------------------
// conv1: 2x2 (ha,wa) tile x 64-lane chunk. 256 threads = 4 co-groups (8 co)
// x 4 positions x 16 lane-groups (4 lanes, float4). Per thread per ci:
// 27 LDS.128 feed 288 FFMAs (2x denser than R6). smem 164 KB -> 1 CTA.
// ---------------------------------------------------------------------------
__global__ __launch_bounds__(256)
void conv1_kernel(const float* __restrict__ w1, const float* __restrict__ b1,
                  float* __restrict__ out) {
    extern __shared__ float sm[];
    float* s_in = sm;                   // [16 coords][32 ci][64 lanes] = 32768
    float* s_w  = sm + 32768;           // [ci][tap][co] = 9216
    float* s_sc = sm + 32768 + 9216;    // 32
    float* s_sh = s_sc + 32;            // 32

    const int bid   = blockIdx.x;
    const int b     = bid / 1296;
    const int r     = bid - b * 1296;
    const int tile  = r / 9, chunk = r - (r / 9) * 9;
    const int ha0   = (tile / 12) * 2, wa0 = (tile % 12) * 2;
    const int lane0 = chunk * 64;
    const int tid   = threadIdx.x;

    if (tid < 32) {
        s_sc[tid] = g_scale[b * 32 + tid];
        s_sh[tid] = g_shift[b * 32 + tid];
    }
    for (int i = tid; i < COUT * 9 * COUT; i += 256) {
        int ci = i / 288; int t = (i >> 5) % 9; int co = i & 31;
        s_w[i] = w1[(co * COUT + ci) * 9 + t];
    }
    __syncthreads();

    // stage inputs with GN + ReLU; zero-pad halo
    for (int idx = tid; idx < 16 * 32 * 64; idx += 256) {
        int lane  = idx & 63;
        int ci    = (idx >> 6) & 31;
        int coord = idx >> 11;
        int cy = ha0 - 1 + (coord >> 2);
        int cx = wa0 - 1 + (coord & 3);
        float v = 0.f;
        if ((unsigned)cy < S && (unsigned)cx < S) {
            float m = g_mid[((long)(b * SS + cy * S + cx) * COUT + ci) * SS + lane0 + lane];
            v = fmaxf(fmaf(m, s_sc[ci], s_sh[ci]), 0.f);
        }
        s_in[idx] = v;
    }
    __syncthreads();

    const int cg = tid >> 6;          // warp-uniform co-group (8 co)
    const int rp = tid & 63;
    const int p  = rp >> 4;           // 0..3 -> (py,px) in 2x2
    const int lg = rp & 15;           // 16 lane-groups x 4 lanes
    const int py = p >> 1, px = p & 1;
    const int l0 = lg * 4;
    const int co0 = cg * 8;

    float acc[8][4];
    #pragma unroll
    for (int j = 0; j < 8; j++) {
        float bb = __ldg(&b1[co0 + j]);
        acc[j][0] = bb; acc[j][1] = bb; acc[j][2] = bb; acc[j][3] = bb;
    }

    for (int ci = 0; ci < COUT; ci++) {
        float4 in4[3][3];
        #pragma unroll
        for (int ky = 0; ky < 3; ky++)
            #pragma unroll
            for (int kx = 0; kx < 3; kx++) {
                int coord = (py + ky) * 4 + px + kx;
                in4[ky][kx] = *(const float4*)&s_in[(coord * 32 + ci) * 64 + l0];
            }
        #pragma unroll
        for (int ky = 0; ky < 3; ky++)
          #pragma unroll
          for (int kx = 0; kx < 3; kx++) {
            int t = ky * 3 + kx;
            float4 wA = *(const float4*)&s_w[ci * 288 + t * 32 + co0];
            float4 wB = *(const float4*)&s_w[ci * 288 + t * 32 + co0 + 4];
            float4 v = in4[ky][kx];
            acc[0][0] += v.x * wA.x; acc[0][1] += v.y * wA.x; acc[0][2] += v.z * wA.x; acc[0][3] += v.w * wA.x;
            acc[1][0] += v.x * wA.y; acc[1][1] += v.y * wA.y; acc[1][2] += v.z * wA.y; acc[1][3] += v.w * wA.y;
            acc[2][0] += v.x * wA.z; acc[2][1] += v.y * wA.z; acc[2][2] += v.z * wA.z; acc[2][3] += v.w * wA.z;
            acc[3][0] += v.x * wA.w; acc[3][1] += v.y * wA.w; acc[3][2] += v.z * wA.w; acc[3][3] += v.w * wA.w;
            acc[4][0] += v.x * wB.x; acc[4][1] += v.y * wB.x; acc[4][2] += v.z * wB.x; acc[4][3] += v.w * wB.x;
            acc[5][0] += v.x * wB.y; acc[5][1] += v.y * wB.y; acc[5][2] += v.z * wB.y; acc[5][3] += v.w * wB.y;
            acc[6][0] += v.x * wB.z; acc[6][1] += v.y * wB.z; acc[6][2] += v.z * wB.z; acc[6][3] += v.w * wB.z;
            acc[7][0] += v.x * wB.w; acc[7][1] += v.y * wB.w; acc[7][2] += v.z * wB.w; acc[7][3] += v.w * wB.w;
          }
    }

    const int hawa = (ha0 + py) * S + wa0 + px;
    #pragma unroll
    for (int j = 0; j < 8; j++) {
        float4 o = make_float4(acc[j][0], acc[j][1], acc[j][2], acc[j][3]);
        *(float4*)&out[((long)(b * COUT + co0 + j) * SS + hawa) * SS + lane0 + l0] = o;
    }
}

// ---------------------------------------------------------------------------
extern "C" void kernel_launch(void* const* d_in, const int* in_sizes, int n_in,
                              void* d_out, int out_size) {
    const float* x   = (const float*)d_in[0];
    const float* w1  = (const float*)d_in[1];
    const float* b1  = (const float*)d_in[2];
    const float* w2  = (const float*)d_in[3];
    const float* b2  = (const float*)d_in[4];
    const float* gam = (const float*)d_in[5];
    const float* bet = (const float*)d_in[6];
    float* out = (float*)d_out;

    const int smem2 = (10816 + 4608 + 8) * 4;           // 61,728 B
    const int smem1 = (32768 + 9216 + 64) * 4;          // 168,192 B
    cudaFuncSetAttribute(conv2_kernel, cudaFuncAttributeMaxDynamicSharedMemorySize, smem2);
    cudaFuncSetAttribute(conv1_kernel, cudaFuncAttributeMaxDynamicSharedMemorySize, smem1);

    zero_stats_kernel<<<1, 64>>>();
    conv2_kernel<<<BSZ * SS, 512, smem2>>>(x, w2, b2);
    finalize_kernel<<<1, 256>>>(gam, bet);
    conv1_kernel<<<BSZ * 144 * 9, 256, smem1>>>(w1, b1, out);
}

// round 11
// speedup vs baseline: 1.7282x; 1.7282x over previous
#include <cuda_runtime.h>

#define CIN  16
#define COUT 32
#define BSZ  8
#define S    24
#define SS   576
#define EPS  1e-5f

__device__ float g_mid[BSZ * SS * COUT * SS];
__device__ float g_stats[BSZ * 4 * 2];
__device__ float g_scale[BSZ * COUT];
__device__ float g_shift[BSZ * COUT];

__global__ void zero_stats_kernel() {
    if (threadIdx.x < BSZ * 8) g_stats[threadIdx.x] = 0.f;
}

// ---------------------------------------------------------------------------
// conv2: identical to the passing R6 version.
// ---------------------------------------------------------------------------
__global__ __launch_bounds__(512, 1)
void conv2_kernel(const float* __restrict__ x, const float* __restrict__ w2,
                  const float* __restrict__ b2) {
    extern __shared__ float sm[];
    float* s_img = sm;                  // [16][26][26] = 10816
    float* s_w   = sm + 10816;          // [ci][tap][co] = 4608
    float* s_red = sm + 10816 + 4608;   // 8

    const int bid  = blockIdx.x;
    const int b    = bid / SS;
    const int hawa = bid % SS;
    const int tid  = threadIdx.x;

    if (tid < 8) s_red[tid] = 0.f;
    for (int i = tid; i < CIN * 26 * 26; i += 512) s_img[i] = 0.f;
    for (int i = tid; i < CIN * 9 * COUT; i += 512) {
        int ci = i / 288; int tap = (i >> 5) % 9; int co = i & 31;
        s_w[i] = w2[(co * CIN + ci) * 9 + tap];
    }
    __syncthreads();
    for (int i = tid; i < CIN * SS; i += 512) {
        int ci = i / SS; int p = i - ci * SS;
        int hb = p / S, wb = p - hb * S;
        s_img[ci * 676 + (hb + 1) * 26 + (wb + 1)] =
            x[(((long)b * CIN + ci) * SS + hawa) * SS + p];
    }
    __syncthreads();

    const int cg = tid >> 6;
    const int pt = tid & 63;
    const int py = (pt >> 3) * 3;
    const int px = (pt & 7) * 3;

    float acc[9][4];
    #pragma unroll
    for (int j = 0; j < 4; j++) {
        float bb = __ldg(&b2[cg * 4 + j]);
        #pragma unroll
        for (int p = 0; p < 9; p++) acc[p][j] = bb;
    }

    for (int ci = 0; ci < CIN; ci++) {
        float wr[4][9];
        #pragma unroll
        for (int t = 0; t < 9; t++) {
            float4 wv = *(const float4*)&s_w[(ci * 9 + t) * 32 + cg * 4];
            wr[0][t] = wv.x; wr[1][t] = wv.y; wr[2][t] = wv.z; wr[3][t] = wv.w;
        }
        float in[5][5];
        #pragma unroll
        for (int dy = 0; dy < 5; dy++)
            #pragma unroll
            for (int dx = 0; dx < 5; dx++)
                in[dy][dx] = s_img[ci * 676 + (py + dy) * 26 + (px + dx)];
        #pragma unroll
        for (int oy = 0; oy < 3; oy++)
          #pragma unroll
          for (int ox = 0; ox < 3; ox++)
            #pragma unroll
            for (int ky = 0; ky < 3; ky++)
              #pragma unroll
              for (int kx = 0; kx < 3; kx++) {
                float v = in[oy + ky][ox + kx];
                int t = ky * 3 + kx;
                #pragma unroll
                for (int j = 0; j < 4; j++)
                    acc[oy * 3 + ox][j] += v * wr[j][t];
              }
    }

    float s = 0.f, sq = 0.f;
    float* midb = g_mid + (long)(b * SS + hawa) * COUT * SS;
    #pragma unroll
    for (int oy = 0; oy < 3; oy++)
      #pragma unroll
      for (int ox = 0; ox < 3; ox++) {
        int hbwb = (py + oy) * S + (px + ox);
        #pragma unroll
        for (int j = 0; j < 4; j++) {
            float v = acc[oy * 3 + ox][j];
            s += v; sq += v * v;
            midb[(cg * 4 + j) * SS + hbwb] = v;
        }
      }
    atomicAdd(&s_red[(cg >> 1) * 2],     s);
    atomicAdd(&s_red[(cg >> 1) * 2 + 1], sq);
    __syncthreads();
    if (tid < 8) atomicAdd(&g_stats[b * 8 + tid], s_red[tid]);
}

// ---------------------------------------------------------------------------
__global__ void finalize_kernel(const float* __restrict__ gamma,
                                const float* __restrict__ beta) {
    int tid = threadIdx.x;
    if (tid >= BSZ * COUT) return;
    int b = tid >> 5, c = tid & 31, g = c >> 3;
    const float n = (float)(8 * SS * SS);
    float s  = g_stats[b * 8 + g * 2];
    float ss = g_stats[b * 8 + g * 2 + 1];
    float mean = s / n;
    float var  = ss / n - mean * mean;
    float sc = gamma[c] * rsqrtf(var + EPS);
    g_scale[tid] = sc;
    g_shift[tid] = beta[c] - mean * sc;
}

// ---------------------------------------------------------------------------
// conv1: R6 structure (2x2 tile, 32-lane chunk, 256 threads, float2 lanes)
// with weights staged in four 8-ci chunks: smem 102.6 KB -> 73.2 KB,
// 3 CTAs/SM = 24 warps.
// ---------------------------------------------------------------------------
__global__ __launch_bounds__(256, 3)
void conv1_kernel(const float* __restrict__ w1, const float* __restrict__ b1,
                  float* __restrict__ out) {
    extern __shared__ float sm[];
    float* s_in = sm;                   // [16 coords][32 ci][32 lanes] = 16384
    float* s_w  = sm + 16384;           // [8 ci][9 tap][32 co] = 2304
    float* s_sc = sm + 16384 + 2304;    // 32
    float* s_sh = s_sc + 32;            // 32

    const int bid   = blockIdx.x;
    const int b     = bid / 2592;
    const int r     = bid - b * 2592;
    const int tile  = r / 18, chunk = r - (r / 18) * 18;
    const int ha0   = (tile / 12) * 2, wa0 = (tile % 12) * 2;
    const int lane0 = chunk * 32;
    const int tid   = threadIdx.x;

    if (tid < 32) {
        s_sc[tid] = g_scale[b * 32 + tid];
        s_sh[tid] = g_shift[b * 32 + tid];
    }
    __syncthreads();

    for (int idx = tid; idx < 16 * 32 * 32; idx += 256) {
        int lane  = idx & 31;
        int ci    = (idx >> 5) & 31;
        int coord = idx >> 10;
        int cy = ha0 - 1 + (coord >> 2);
        int cx = wa0 - 1 + (coord & 3);
        float v = 0.f;
        if ((unsigned)cy < S && (unsigned)cx < S) {
            float m = g_mid[((long)(b * SS + cy * S + cx) * COUT + ci) * SS + lane0 + lane];
            v = fmaxf(fmaf(m, s_sc[ci], s_sh[ci]), 0.f);
        }
        s_in[idx] = v;
    }

    const int cg = tid >> 6;          // warp-uniform co-group (8 co)
    const int rp = tid & 63;
    const int p  = rp >> 4;           // 0..3 -> (py,px) in 2x2
    const int lg = rp & 15;           // 16 lane-groups x 2 lanes
    const int py = p >> 1, px = p & 1;
    const int l0 = lg * 2;
    const int co0 = cg * 8;

    float acc[8][2];
    #pragma unroll
    for (int j = 0; j < 8; j++) {
        float bb = __ldg(&b1[co0 + j]);
        acc[j][0] = bb; acc[j][1] = bb;
    }

    for (int c4 = 0; c4 < 4; c4++) {
        __syncthreads();   // prev s_w chunk fully consumed / s_in staged
        for (int i = tid; i < 8 * 9 * COUT; i += 256) {
            int ci = (i / 288) + c4 * 8; int t = (i >> 5) % 9; int co = i & 31;
            s_w[i] = w1[(co * COUT + ci) * 9 + t];
        }
        __syncthreads();

        for (int ci8 = 0; ci8 < 8; ci8++) {
            int ci = c4 * 8 + ci8;
            float2 in2[3][3];
            #pragma unroll
            for (int ky = 0; ky < 3; ky++)
                #pragma unroll
                for (int kx = 0; kx < 3; kx++) {
                    int coord = (py + ky) * 4 + px + kx;
                    in2[ky][kx] = *(const float2*)&s_in[(coord * 32 + ci) * 32 + l0];
                }
            #pragma unroll
            for (int ky = 0; ky < 3; ky++)
              #pragma unroll
              for (int kx = 0; kx < 3; kx++) {
                int t = ky * 3 + kx;
                float4 wA = *(const float4*)&s_w[ci8 * 288 + t * 32 + co0];
                float4 wB = *(const float4*)&s_w[ci8 * 288 + t * 32 + co0 + 4];
                float ix = in2[ky][kx].x, iy = in2[ky][kx].y;
                acc[0][0] += ix * wA.x;  acc[0][1] += iy * wA.x;
                acc[1][0] += ix * wA.y;  acc[1][1] += iy * wA.y;
                acc[2][0] += ix * wA.z;  acc[2][1] += iy * wA.z;
                acc[3][0] += ix * wA.w;  acc[3][1] += iy * wA.w;
                acc[4][0] += ix * wB.x;  acc[4][1] += iy * wB.x;
                acc[5][0] += ix * wB.y;  acc[5][1] += iy * wB.y;
                acc[6][0] += ix * wB.z;  acc[6][1] += iy * wB.z;
                acc[7][0] += ix * wB.w;  acc[7][1] += iy * wB.w;
              }
        }
    }

    const int hawa = (ha0 + py) * S + wa0 + px;
    #pragma unroll
    for (int j = 0; j < 8; j++) {
        float2 o = make_float2(acc[j][0], acc[j][1]);
        *(float2*)&out[((long)(b * COUT + co0 + j) * SS + hawa) * SS + lane0 + l0] = o;
    }
}

// ---------------------------------------------------------------------------
extern "C" void kernel_launch(void* const* d_in, const int* in_sizes, int n_in,
                              void* d_out, int out_size) {
    const float* x   = (const float*)d_in[0];
    const float* w1  = (const float*)d_in[1];
    const float* b1  = (const float*)d_in[2];
    const float* w2  = (const float*)d_in[3];
    const float* b2  = (const float*)d_in[4];
    const float* gam = (const float*)d_in[5];
    const float* bet = (const float*)d_in[6];
    float* out = (float*)d_out;

    const int smem2 = (10816 + 4608 + 8) * 4;            // 61,728 B
    const int smem1 = (16384 + 2304 + 64) * 4;           // 75,008 B
    cudaFuncSetAttribute(conv2_kernel, cudaFuncAttributeMaxDynamicSharedMemorySize, smem2);
    cudaFuncSetAttribute(conv1_kernel, cudaFuncAttributeMaxDynamicSharedMemorySize, smem1);

    zero_stats_kernel<<<1, 64>>>();
    conv2_kernel<<<BSZ * SS, 512, smem2>>>(x, w2, b2);
    finalize_kernel<<<1, 256>>>(gam, bet);
    conv1_kernel<<<BSZ * 144 * 18, 256, smem1>>>(w1, b1, out);
}